// round 13
// baseline (speedup 1.0000x reference)
#include <cuda_runtime.h>
#include <cuda_bf16.h>

#define NUM_P 196          // 14*14 patch locations

// ---------------------------------------------------------------------------
// Scalar gate helpers (16 amplitudes in registers, fully unrolled).
// amplitude index bits: 8=wire0, 4=wire1, 2=wire2, 1=wire3
// ---------------------------------------------------------------------------
template <int M>
__device__ __forceinline__ void ry_real(float* a, float c, float s) {
#pragma unroll
    for (int i = 0; i < 16; i++)
        if (!(i & M)) {
            const int j = i | M;
            float a0 = a[i], a1 = a[j];
            a[i] = c * a0 - s * a1;
            a[j] = s * a0 + c * a1;
        }
}

template <int M>
__device__ __forceinline__ void ry_cplx(float* ar, float* ai, float c, float s) {
#pragma unroll
    for (int i = 0; i < 16; i++)
        if (!(i & M)) {
            const int j = i | M;
            float r0 = ar[i], r1 = ar[j];
            ar[i] = c * r0 - s * r1;
            ar[j] = s * r0 + c * r1;
            float i0 = ai[i], i1 = ai[j];
            ai[i] = c * i0 - s * i1;
            ai[j] = s * i0 + c * i1;
        }
}

template <int MC, int MT>
__device__ __forceinline__ void cnot_real(float* a) {
#pragma unroll
    for (int i = 0; i < 16; i++)
        if ((i & MC) && !(i & MT)) {
            const int j = i | MT;
            float t = a[i]; a[i] = a[j]; a[j] = t;   // register rename, free
        }
}

template <int MC, int MT>
__device__ __forceinline__ void cnot_cplx(float* ar, float* ai) {
    cnot_real<MC, MT>(ar);
    cnot_real<MC, MT>(ai);
}

// build real product state from cw/sw
__device__ __forceinline__ void init_state(float* ar, const float* cw, const float* sw) {
    float f01[4] = { cw[0] * cw[1], cw[0] * sw[1], sw[0] * cw[1], sw[0] * sw[1] };
    float f23[4] = { cw[2] * cw[3], cw[2] * sw[3], sw[2] * cw[3], sw[2] * sw[3] };
#pragma unroll
    for (int hi = 0; hi < 4; hi++)
#pragma unroll
        for (int lo = 0; lo < 4; lo++)
            ar[hi * 4 + lo] = f01[hi] * f23[lo];
}

// Walsh-Hadamard Z-reduction from 16 probabilities
__device__ __forceinline__ float4 wh_z(const float* pv) {
    float a8[8], d8[8];
#pragma unroll
    for (int k = 0; k < 8; k++) { a8[k] = pv[2*k] + pv[2*k+1]; d8[k] = pv[2*k] - pv[2*k+1]; }
    float z3 = ((d8[0] + d8[1]) + (d8[2] + d8[3])) + ((d8[4] + d8[5]) + (d8[6] + d8[7]));
    float b4[4], e4[4];
#pragma unroll
    for (int j = 0; j < 4; j++) { b4[j] = a8[2*j] + a8[2*j+1]; e4[j] = a8[2*j] - a8[2*j+1]; }
    float z2 = (e4[0] + e4[1]) + (e4[2] + e4[3]);
    float z1 = (b4[0] - b4[1]) + (b4[2] - b4[3]);
    float z0 = (b4[0] + b4[1]) - (b4[2] + b4[3]);
    return make_float4(z0, z1, z2, z3);
}

// ---------------------------------------------------------------------------
// Fused kernel: 392 blocks x 128 threads; block = (patch p, batch half).
// Phase A: redundant per-block stats over all 512 samples (4 loads/thread).
// Phase B: TWO independent circuits per thread (ILP), samples cb and cb+128.
// ---------------------------------------------------------------------------
__global__ void __launch_bounds__(128)
qf_fused2_kernel(const float* __restrict__ x,
                 const float* __restrict__ params,
                 float* __restrict__ out) {
    __shared__ float sh_s[4], sh_q[4];
    __shared__ float sP0[4];              // params[0][w][0] (merged into input RY)
    __shared__ float2 sCS[12];            // {cos,sin}: [col*4+wire], col: l0c1,l1c0,l1c1
    __shared__ float2 sPh[16];            // layer-0 RZ phasors {pr, pi}

    const int p    = blockIdx.x >> 1;
    const int half = blockIdx.x & 1;
    const int r = p / 14, c = p % 14;
    const int tid = threadIdx.x;
    const int lane = tid & 31, wid = tid >> 5;
    const int poff = (2 * r) * 28 + 2 * c;

    // --- load 4 samples' patches: rows tid, tid+128, tid+256, tid+384 ---
    float v[4][4];
    const float* xb = x + tid * 784 + poff;
#pragma unroll
    for (int g = 0; g < 4; g++) {
        v[g][0] = xb[0]; v[g][1] = xb[1]; v[g][2] = xb[28]; v[g][3] = xb[29];
        xb += 128 * 784;
    }

    // --- Phase A: stats over all 512 samples (2048 values) ---
    float s = 0.f, q = 0.f;
#pragma unroll
    for (int g = 0; g < 4; g++) {
        s += (v[g][0] + v[g][1]) + (v[g][2] + v[g][3]);
        q += v[g][0] * v[g][0] + v[g][1] * v[g][1]
           + v[g][2] * v[g][2] + v[g][3] * v[g][3];
    }
#pragma unroll
    for (int o = 16; o > 0; o >>= 1) {
        s += __shfl_down_sync(0xffffffffu, s, o);
        q += __shfl_down_sync(0xffffffffu, q, o);
    }
    if (lane == 0) { sh_s[wid] = s; sh_q[wid] = q; }

    // --- params precompute, parallel across warp 1 lanes ---
    if (wid == 1) {
        if (lane < 16) {              // one RZ phasor per lane
            float prr = 1.f, pii = 0.f;
#pragma unroll
            for (int w = 0; w < 4; w++) {
                float szv, czv;
                __sincosf(0.5f * params[w * 3 + 2], &szv, &czv);
                float sw_ = (lane & (8 >> w)) ? szv : -szv;
                float nr = prr * czv - pii * sw_;
                pii = prr * sw_ + pii * czv;
                prr = nr;
            }
            sPh[lane] = make_float2(prr, pii);
        } else if (lane < 28) {       // 12 RY gate constants
            int j = lane - 16;
            int col = j >> 2, wire = j & 3;
            int pidx = (col == 0) ? wire * 3 + 1
                     : (col == 1) ? 12 + wire * 3
                                  : 12 + wire * 3 + 1;
            float s_, c_;
            __sincosf(0.5f * params[pidx], &s_, &c_);
            sCS[j] = make_float2(c_, s_);
        } else {                      // merged first RY column angles
            int wire = lane - 28;
            sP0[wire] = params[wire * 3 + 0];
        }
    }
    __syncthreads();

    // redundant final reduce (LDS broadcast; no second barrier)
    float fs = (sh_s[0] + sh_s[1]) + (sh_s[2] + sh_s[3]);
    float fq = (sh_q[0] + sh_q[1]) + (sh_q[2] + sh_q[3]);
    const float n = 2048.0f;
    const float mean = fs / n;
    const float var = fmaxf((fq - fs * mean) / (n - 1.0f), 0.0f);
    const float inv = 3.14159265358979323846f / (sqrtf(var) + 1e-8f);

    // --- Phase B: two circuits. samples cb0 = half*256+tid, cb1 = cb0+128 ---
    // their patch values are loads #(2*half) and #(2*half+1)
    const float* u0 = v[2 * half];
    const float* u1 = v[2 * half + 1];

    float cwA[4], swA[4], cwB[4], swB[4];
#pragma unroll
    for (int w = 0; w < 4; w++) {
        __sincosf(0.5f * ((u0[w] - mean) * inv + sP0[w]), &swA[w], &cwA[w]);
        __sincosf(0.5f * ((u1[w] - mean) * inv + sP0[w]), &swB[w], &cwB[w]);
    }

    float arA[16], aiA[16], arB[16], aiB[16];
    init_state(arA, cwA, swA);
    init_state(arB, cwB, swB);

    // ---- layer 0 remainder (real) ----
    cnot_real<8, 4>(arA); cnot_real<4, 2>(arA); cnot_real<2, 1>(arA);
    cnot_real<8, 4>(arB); cnot_real<4, 2>(arB); cnot_real<2, 1>(arB);
    {
        float2 g0 = sCS[0], g1 = sCS[1], g2 = sCS[2], g3 = sCS[3];
        ry_real<8>(arA, g0.x, g0.y);  ry_real<8>(arB, g0.x, g0.y);
        ry_real<4>(arA, g1.x, g1.y);  ry_real<4>(arB, g1.x, g1.y);
        ry_real<2>(arA, g2.x, g2.y);  ry_real<2>(arB, g2.x, g2.y);
        ry_real<1>(arA, g3.x, g3.y);  ry_real<1>(arB, g3.x, g3.y);
    }
    cnot_real<4, 8>(arA); cnot_real<2, 4>(arA); cnot_real<1, 2>(arA);
    cnot_real<4, 8>(arB); cnot_real<2, 4>(arB); cnot_real<1, 2>(arB);

    // RZ: real -> complex via precomputed phasors
#pragma unroll
    for (int idx = 0; idx < 16; idx++) {
        float2 ph = sPh[idx];
        aiA[idx] = arA[idx] * ph.y;  arA[idx] = arA[idx] * ph.x;
        aiB[idx] = arB[idx] * ph.y;  arB[idx] = arB[idx] * ph.x;
    }

    // ---- layer 1 (complex; final RZ is pure phase -> skipped) ----
    {
        float2 g0 = sCS[4], g1 = sCS[5], g2 = sCS[6], g3 = sCS[7];
        ry_cplx<8>(arA, aiA, g0.x, g0.y);  ry_cplx<8>(arB, aiB, g0.x, g0.y);
        ry_cplx<4>(arA, aiA, g1.x, g1.y);  ry_cplx<4>(arB, aiB, g1.x, g1.y);
        ry_cplx<2>(arA, aiA, g2.x, g2.y);  ry_cplx<2>(arB, aiB, g2.x, g2.y);
        ry_cplx<1>(arA, aiA, g3.x, g3.y);  ry_cplx<1>(arB, aiB, g3.x, g3.y);
    }
    cnot_cplx<8, 4>(arA, aiA); cnot_cplx<4, 2>(arA, aiA); cnot_cplx<2, 1>(arA, aiA);
    cnot_cplx<8, 4>(arB, aiB); cnot_cplx<4, 2>(arB, aiB); cnot_cplx<2, 1>(arB, aiB);
    {
        float2 g0 = sCS[8], g1 = sCS[9], g2 = sCS[10], g3 = sCS[11];
        ry_cplx<8>(arA, aiA, g0.x, g0.y);  ry_cplx<8>(arB, aiB, g0.x, g0.y);
        ry_cplx<4>(arA, aiA, g1.x, g1.y);  ry_cplx<4>(arB, aiB, g1.x, g1.y);
        ry_cplx<2>(arA, aiA, g2.x, g2.y);  ry_cplx<2>(arB, aiB, g2.x, g2.y);
        ry_cplx<1>(arA, aiA, g3.x, g3.y);  ry_cplx<1>(arB, aiB, g3.x, g3.y);
    }
    cnot_cplx<4, 8>(arA, aiA); cnot_cplx<2, 4>(arA, aiA); cnot_cplx<1, 2>(arA, aiA);
    cnot_cplx<4, 8>(arB, aiB); cnot_cplx<2, 4>(arB, aiB); cnot_cplx<1, 2>(arB, aiB);

    // ---- probabilities + Z reduction ----
    float pvA[16], pvB[16];
#pragma unroll
    for (int idx = 0; idx < 16; idx++) {
        pvA[idx] = fmaf(arA[idx], arA[idx], aiA[idx] * aiA[idx]);
        pvB[idx] = fmaf(arB[idx], arB[idx], aiB[idx] * aiB[idx]);
    }
    float4 zA = wh_z(pvA);
    float4 zB = wh_z(pvB);

    const int cb0 = half * 256 + tid;
    *reinterpret_cast<float4*>(out + cb0 * 784 + p * 4) = zA;
    *reinterpret_cast<float4*>(out + (cb0 + 128) * 784 + p * 4) = zB;
}

// ---------------------------------------------------------------------------
extern "C" void kernel_launch(void* const* d_in, const int* in_sizes, int n_in,
                              void* d_out, int out_size) {
    const float* x = (const float*)d_in[0];
    const float* params = (const float*)d_in[1];
    if (n_in >= 2 && in_sizes[0] == 24) {   // robustness vs input ordering
        x = (const float*)d_in[1];
        params = (const float*)d_in[0];
    }
    float* out = (float*)d_out;

    qf_fused2_kernel<<<2 * NUM_P, 128>>>(x, params, out);
}

// round 14
// speedup vs baseline: 1.0208x; 1.0208x over previous
#include <cuda_runtime.h>
#include <cuda_bf16.h>

#define NUM_P 196          // 14*14 patch locations

// ---------------------------------------------------------------------------
// Gate helpers (16 amplitudes in registers, fully unrolled).
// amplitude index bits: 8=wire0, 4=wire1, 2=wire2, 1=wire3
// Classic: g = {cos(th/2)... wait per-gate {c,s} of half?  NOTE: gates use
// c = cos(theta/2), s = sin(theta/2) of the *circuit* convention (RY(theta)
// mixes with cos/sin of theta/2).  Shear: g = {t, s_f} with t = tan(theta/4)?
// No: rotation angle in the 2x2 block is theta/2, so classic {c,s} =
// {cos(th/2), sin(th/2)}, shear t = tan(th/4), s_f = sin(th/2).
// ---------------------------------------------------------------------------
template <int M, bool SH>
__device__ __forceinline__ void ry_real(float* a, float2 g) {
#pragma unroll
    for (int i = 0; i < 16; i++)
        if (!(i & M)) {
            const int j = i | M;
            float a0 = a[i], a1 = a[j];
            if (SH) {
                float x = fmaf(-g.x, a1, a0);
                float y = fmaf(g.y, x, a1);
                a[i] = fmaf(-g.x, y, x);
                a[j] = y;
            } else {
                a[i] = g.x * a0 - g.y * a1;
                a[j] = g.y * a0 + g.x * a1;
            }
        }
}

template <int M, bool SH>
__device__ __forceinline__ void ry_cplx(float* ar, float* ai, float2 g) {
#pragma unroll
    for (int i = 0; i < 16; i++)
        if (!(i & M)) {
            const int j = i | M;
            float r0 = ar[i], r1 = ar[j];
            float i0 = ai[i], i1 = ai[j];
            if (SH) {
                float xr = fmaf(-g.x, r1, r0);
                float yr = fmaf(g.y, xr, r1);
                ar[i] = fmaf(-g.x, yr, xr);
                ar[j] = yr;
                float xi = fmaf(-g.x, i1, i0);
                float yi = fmaf(g.y, xi, i1);
                ai[i] = fmaf(-g.x, yi, xi);
                ai[j] = yi;
            } else {
                ar[i] = g.x * r0 - g.y * r1;
                ar[j] = g.y * r0 + g.x * r1;
                ai[i] = g.x * i0 - g.y * i1;
                ai[j] = g.y * i0 + g.x * i1;
            }
        }
}

template <int MC, int MT>
__device__ __forceinline__ void cnot_real(float* a) {
#pragma unroll
    for (int i = 0; i < 16; i++)
        if ((i & MC) && !(i & MT)) {
            const int j = i | MT;
            float t = a[i]; a[i] = a[j]; a[j] = t;   // register rename, free
        }
}

template <int MC, int MT>
__device__ __forceinline__ void cnot_cplx(float* ar, float* ai) {
    cnot_real<MC, MT>(ar);
    cnot_real<MC, MT>(ai);
}

// ---------------------------------------------------------------------------
// Circuit body (templated on shear vs classic gate form)
// ---------------------------------------------------------------------------
template <bool SH>
__device__ __forceinline__ float4
run_circuit(const float* cw, const float* sw, const float2* sCS, const float2* sPh) {
    // product state (real); input RY + layer-0 col0 already merged in angles
    float ar[16], ai[16];
    {
        float f01[4] = { cw[0] * cw[1], cw[0] * sw[1], sw[0] * cw[1], sw[0] * sw[1] };
        float f23[4] = { cw[2] * cw[3], cw[2] * sw[3], sw[2] * cw[3], sw[2] * sw[3] };
#pragma unroll
        for (int hi = 0; hi < 4; hi++)
#pragma unroll
            for (int lo = 0; lo < 4; lo++)
                ar[hi * 4 + lo] = f01[hi] * f23[lo];
    }

    // ---- layer 0 remainder (real) ----
    cnot_real<8, 4>(ar); cnot_real<4, 2>(ar); cnot_real<2, 1>(ar);
    ry_real<8, SH>(ar, sCS[0]);
    ry_real<4, SH>(ar, sCS[1]);
    ry_real<2, SH>(ar, sCS[2]);
    ry_real<1, SH>(ar, sCS[3]);
    cnot_real<4, 8>(ar); cnot_real<2, 4>(ar); cnot_real<1, 2>(ar);

    // RZ: real -> complex via precomputed phasors
#pragma unroll
    for (int idx = 0; idx < 16; idx++) {
        float2 ph = sPh[idx];
        ai[idx] = ar[idx] * ph.y;
        ar[idx] = ar[idx] * ph.x;
    }

    // ---- layer 1 (complex; final RZ is pure phase -> skipped) ----
    ry_cplx<8, SH>(ar, ai, sCS[4]);
    ry_cplx<4, SH>(ar, ai, sCS[5]);
    ry_cplx<2, SH>(ar, ai, sCS[6]);
    ry_cplx<1, SH>(ar, ai, sCS[7]);
    cnot_cplx<8, 4>(ar, ai); cnot_cplx<4, 2>(ar, ai); cnot_cplx<2, 1>(ar, ai);
    ry_cplx<8, SH>(ar, ai, sCS[8]);
    ry_cplx<4, SH>(ar, ai, sCS[9]);
    ry_cplx<2, SH>(ar, ai, sCS[10]);
    ry_cplx<1, SH>(ar, ai, sCS[11]);
    cnot_cplx<4, 8>(ar, ai); cnot_cplx<2, 4>(ar, ai); cnot_cplx<1, 2>(ar, ai);

    // ---- probabilities ----
    float pv[16];
#pragma unroll
    for (int idx = 0; idx < 16; idx++)
        pv[idx] = fmaf(ar[idx], ar[idx], ai[idx] * ai[idx]);

    // ---- Z expectations via Walsh-Hadamard tree ----
    float a8[8], d8[8];
#pragma unroll
    for (int k = 0; k < 8; k++) { a8[k] = pv[2*k] + pv[2*k+1]; d8[k] = pv[2*k] - pv[2*k+1]; }
    float z3 = ((d8[0] + d8[1]) + (d8[2] + d8[3])) + ((d8[4] + d8[5]) + (d8[6] + d8[7]));
    float b4[4], e4[4];
#pragma unroll
    for (int j = 0; j < 4; j++) { b4[j] = a8[2*j] + a8[2*j+1]; e4[j] = a8[2*j] - a8[2*j+1]; }
    float z2 = (e4[0] + e4[1]) + (e4[2] + e4[3]);
    float z1 = (b4[0] - b4[1]) + (b4[2] - b4[3]);
    float z0 = (b4[0] + b4[1]) - (b4[2] + b4[3]);
    return make_float4(z0, z1, z2, z3);
}

// ---------------------------------------------------------------------------
// Fused kernel: 392 blocks x 256 threads. block = (patch p, batch half).
// Phase A: redundant per-block stats over all 512 samples (single barrier).
// Phase B: one circuit per thread (sample = half*256 + tid).
// ---------------------------------------------------------------------------
__global__ void __launch_bounds__(256)
qf_fused_kernel(const float* __restrict__ x,
                const float* __restrict__ params,
                float* __restrict__ out) {
    __shared__ float sh_s[8], sh_q[8];
    __shared__ float sP0[4];              // params[0][w][0] (merged into input RY)
    __shared__ float2 sCS[12];            // gate consts: shear {t,s} or classic {c,s}
    __shared__ float2 sPh[16];            // layer-0 RZ phasors {pr, pi}
    __shared__ int   sShear;              // 1 = all gates safe for shear form

    const int p    = blockIdx.x >> 1;
    const int half = blockIdx.x & 1;
    const int r = p / 14, c = p % 14;
    const int tid = threadIdx.x;
    const int lane = tid & 31, wid = tid >> 5;

    // --- load two samples' 2x2 patches (rows tid and tid+256) ---
    const float* x0 = x + tid * 784 + (2 * r) * 28 + 2 * c;
    const float* x1 = x0 + 256 * 784;
    float w0 = x0[0], w1 = x0[1], w2 = x0[28], w3 = x0[29];
    float y0 = x1[0], y1 = x1[1], y2 = x1[28], y3 = x1[29];

    // --- Phase A: stats over all 512 samples (2048 values) ---
    float s = ((w0 + w1) + (w2 + w3)) + ((y0 + y1) + (y2 + y3));
    float q = (w0 * w0 + w1 * w1 + w2 * w2 + w3 * w3)
            + (y0 * y0 + y1 * y1 + y2 * y2 + y3 * y3);
#pragma unroll
    for (int o = 16; o > 0; o >>= 1) {
        s += __shfl_down_sync(0xffffffffu, s, o);
        q += __shfl_down_sync(0xffffffffu, q, o);
    }
    if (lane == 0) { sh_s[wid] = s; sh_q[wid] = q; }

    // --- params precompute, parallel across warp 1 lanes ---
    if (wid == 1) {
        bool bad = false;
        float tval = 0.f, sfull = 0.f, cc = 1.f, ss = 0.f;
        if (lane >= 16 && lane < 28) {    // 12 RY gate constants
            int j = lane - 16;
            int col = j >> 2, wire = j & 3;
            int pidx = (col == 0) ? wire * 3 + 1
                     : (col == 1) ? 12 + wire * 3
                                  : 12 + wire * 3 + 1;
            float th2 = 0.5f * params[pidx];       // rotation angle in the 2x2 block
            __sincosf(th2, &ss, &cc);              // classic {c,s}
            float s4, c4;
            __sincosf(0.5f * th2, &s4, &c4);       // quarter angle for t
            tval = __fdividef(s4, c4);             // tan(theta/4)
            sfull = ss;                            // sin(theta/2)
            bad = !(fabsf(tval) <= 8.0f);          // catches NaN too
        }
        unsigned bb = __ballot_sync(0xffffffffu, bad);
        bool shear_ok = (bb & 0x0FFF0000u) == 0u;
        if (lane < 16) {                  // one RZ phasor per lane
            float prr = 1.f, pii = 0.f;
#pragma unroll
            for (int w = 0; w < 4; w++) {
                float szv, czv;
                __sincosf(0.5f * params[w * 3 + 2], &szv, &czv);
                float sw_ = (lane & (8 >> w)) ? szv : -szv;
                float nr = prr * czv - pii * sw_;
                pii = prr * sw_ + pii * czv;
                prr = nr;
            }
            sPh[lane] = make_float2(prr, pii);
            if (lane == 0) sShear = shear_ok ? 1 : 0;
        } else if (lane < 28) {
            sCS[lane - 16] = shear_ok ? make_float2(tval, sfull) : make_float2(cc, ss);
        } else {                          // merged first RY column angles
            sP0[lane - 28] = params[(lane - 28) * 3 + 0];
        }
    }
    __syncthreads();

    // redundant final reduce (LDS broadcast; no second barrier)
    float fs = 0.f, fq = 0.f;
#pragma unroll
    for (int i = 0; i < 8; i++) { fs += sh_s[i]; fq += sh_q[i]; }
    const float mean = fs * (1.0f / 2048.0f);
    const float var = fmaxf((fq - fs * mean) * (1.0f / 2047.0f), 0.0f);
    const float inv = __fdividef(3.14159265358979323846f, sqrtf(var) + 1e-8f);

    // --- Phase B: circuit ---
    float v0 = half ? y0 : w0, v1 = half ? y1 : w1;
    float v2 = half ? y2 : w2, v3 = half ? y3 : w3;

    // input RY merged with layer-0 first RY column
    float cw[4], sw[4];
    __sincosf(0.5f * ((v0 - mean) * inv + sP0[0]), &sw[0], &cw[0]);
    __sincosf(0.5f * ((v1 - mean) * inv + sP0[1]), &sw[1], &cw[1]);
    __sincosf(0.5f * ((v2 - mean) * inv + sP0[2]), &sw[2], &cw[2]);
    __sincosf(0.5f * ((v3 - mean) * inv + sP0[3]), &sw[3], &cw[3]);

    float4 z;
    if (sShear) z = run_circuit<true>(cw, sw, sCS, sPh);
    else        z = run_circuit<false>(cw, sw, sCS, sPh);

    const int b_out = half * 256 + tid;
    *reinterpret_cast<float4*>(out + b_out * 784 + p * 4) = z;
}

// ---------------------------------------------------------------------------
extern "C" void kernel_launch(void* const* d_in, const int* in_sizes, int n_in,
                              void* d_out, int out_size) {
    const float* x = (const float*)d_in[0];
    const float* params = (const float*)d_in[1];
    if (n_in >= 2 && in_sizes[0] == 24) {   // robustness vs input ordering
        x = (const float*)d_in[1];
        params = (const float*)d_in[0];
    }
    float* out = (float*)d_out;

    qf_fused_kernel<<<2 * NUM_P, 256>>>(x, params, out);
}